// round 1
// baseline (speedup 1.0000x reference)
#include <cuda_runtime.h>

#define BB 128
#define GG 16
#define AA 8732
#define CC 21
#define NT 512
#define NWARP (NT/32)

// Per-batch partial results (device globals: no allocation allowed)
__device__ float d_loc[BB];
__device__ float d_cls[BB];
__device__ int   d_npos[BB];

__device__ __forceinline__ float smooth_l1(float d) {
    float ad = fabsf(d);
    return ad < 1.0f ? 0.5f * d * d : ad - 0.5f;
}

__global__ __launch_bounds__(NT) void mb_match_kernel(
    const float4* __restrict__ pred_off,   // [B, A, 4]
    const float*  __restrict__ pred_conf,  // [B, A, C]
    const float4* __restrict__ tboxes,     // [B, G, 4] point form
    const int*    __restrict__ tlabels,    // [B, G]
    const float4* __restrict__ anchors)    // [A, 4] cx,cy,w,h
{
    const int b   = blockIdx.x;
    const int tid = threadIdx.x;
    const int wid = tid >> 5;
    const int lane = tid & 31;

    __shared__ float s_aux[AA];                 // per-anchor aux (nll for negatives)
    __shared__ unsigned char s_meta[AA];        // bits[4:0]=gt index, bit5 = positive
    __shared__ float4 s_box[GG];
    __shared__ int s_lab[GG];
    __shared__ unsigned long long s_best[GG];   // packed per-gt best anchor
    __shared__ float s_wloc[NWARP];
    __shared__ float s_wcls[NWARP];
    __shared__ int   s_wn[NWARP];

    if (tid < GG) {
        s_box[tid]  = tboxes[b * GG + tid];
        s_lab[tid]  = tlabels[b * GG + tid];
        s_best[tid] = 0ull;
    }
    __syncthreads();

    // ---------------- Phase 1: IoU matching ----------------
    unsigned long long lbest[GG];
#pragma unroll
    for (int g = 0; g < GG; ++g) lbest[g] = 0ull;

    for (int a = tid; a < AA; a += NT) {
        float4 an = anchors[a];
        float ax0 = an.x - an.z * 0.5f;
        float ay0 = an.y - an.w * 0.5f;
        float ax1 = an.x + an.z * 0.5f;
        float ay1 = an.y + an.w * 0.5f;
        float area_b = (ax1 - ax0) * (ay1 - ay0);
        float best = -1.0f;
        int bg = 0;
#pragma unroll
        for (int g = 0; g < GG; ++g) {
            float4 bx = s_box[g];
            float w = fminf(bx.z, ax1) - fmaxf(bx.x, ax0);
            float h = fminf(bx.w, ay1) - fmaxf(bx.y, ay0);
            w = fmaxf(w, 0.0f);
            h = fmaxf(h, 0.0f);
            float inter = w * h;
            float area_a = (bx.z - bx.x) * (bx.w - bx.y);
            float iou = inter / (area_a + area_b - inter);
            if (iou > best) { best = iou; bg = g; }   // strict > => first index tie-break (argmax axis=0)
            // per-gt argmax over anchors, lowest anchor index wins ties
            unsigned long long key =
                (((unsigned long long)__float_as_uint(iou)) << 32) |
                (unsigned long long)(0xFFFFFFFFu - (unsigned)a);
            if (key > lbest[g]) lbest[g] = key;
        }
        s_meta[a] = (unsigned char)(bg | (best >= 0.5f ? 0x20 : 0));
    }
#pragma unroll
    for (int g = 0; g < GG; ++g) {
        if (lbest[g] > s_best[g]) atomicMax(&s_best[g], lbest[g]);
    }
    __syncthreads();

    // Sequential forced-match overrides (matches reference's ordered loop)
    if (tid == 0) {
#pragma unroll
        for (int g = 0; g < GG; ++g) {
            unsigned a = 0xFFFFFFFFu - (unsigned)(s_best[g] & 0xFFFFFFFFull);
            s_meta[a] = (unsigned char)(g | 0x20);   // gt_index=g, overlap forced to 1.0
        }
    }
    __syncthreads();

    // ---------------- Phase 2: NLL + loc loss ----------------
    float loc_sum = 0.0f, cls_pos = 0.0f;
    int npos = 0;

    for (int a = tid; a < AA; a += NT) {
        unsigned m = s_meta[a];
        int gi   = m & 0x1F;
        bool pos = (m & 0x20) != 0;
        int cls  = pos ? (s_lab[gi] + 1) : 0;

        const float* row = pred_conf + ((size_t)b * AA + a) * CC;
        float x[CC];
        float mx = -1e30f;
#pragma unroll
        for (int j = 0; j < CC; ++j) {
            x[j] = row[j];
            mx = fmaxf(mx, x[j]);
        }
        float s = 0.0f;
#pragma unroll
        for (int j = 0; j < CC; ++j) s += __expf(x[j] - mx);
        // select x[cls] without dynamic register indexing
        float xc = x[0];
#pragma unroll
        for (int j = 1; j < CC; ++j) xc = (j == cls) ? x[j] : xc;
        float nll = mx + __logf(s) - xc;

        s_aux[a] = pos ? 0.0f : nll;

        if (pos) {
            npos++;
            cls_pos += nll;
            float4 an = anchors[a];
            float4 gb = s_box[gi];
            float l0 = ((gb.x + gb.z) * 0.5f - an.x) / (an.z * 0.1f);
            float l1 = ((gb.y + gb.w) * 0.5f - an.y) / (an.w * 0.1f);
            float l2 = __logf((gb.z - gb.x) / an.z) / 0.2f;
            float l3 = __logf((gb.w - gb.y) / an.w) / 0.2f;
            float4 p = pred_off[(size_t)b * AA + a];
            loc_sum += smooth_l1(p.x - l0) + smooth_l1(p.y - l1) +
                       smooth_l1(p.z - l2) + smooth_l1(p.w - l3);
        }
    }

    // Deterministic block reduction: warp shfl -> per-warp slots -> serial sum
#pragma unroll
    for (int o = 16; o; o >>= 1) {
        loc_sum += __shfl_xor_sync(0xFFFFFFFFu, loc_sum, o);
        cls_pos += __shfl_xor_sync(0xFFFFFFFFu, cls_pos, o);
        npos    += __shfl_xor_sync(0xFFFFFFFFu, npos, o);
    }
    if (lane == 0) { s_wloc[wid] = loc_sum; s_wcls[wid] = cls_pos; s_wn[wid] = npos; }
    __syncthreads();

    float tot_loc = 0.0f, tot_clspos = 0.0f;
    int tot_npos = 0;
#pragma unroll
    for (int w = 0; w < NWARP; ++w) {
        tot_loc += s_wloc[w];
        tot_clspos += s_wcls[w];
        tot_npos += s_wn[w];
    }
    __syncthreads();

    // ---------------- Phase 3: exact top-k sum of aux ----------------
    int k = min(3 * tot_npos, AA - 1);
    float topk = 0.0f;

    if (k > 0) {
        // binary search for the k-th largest value (aux >= 0, bit-compare == float-compare)
        unsigned lo = 0u, hi = 0x7F800001u;
        while (hi - lo > 1u) {
            unsigned mid = lo + ((hi - lo) >> 1);
            int c = 0;
            for (int a = tid; a < AA; a += NT)
                c += (__float_as_uint(s_aux[a]) >= mid) ? 1 : 0;
#pragma unroll
            for (int o = 16; o; o >>= 1) c += __shfl_xor_sync(0xFFFFFFFFu, c, o);
            if (lane == 0) s_wn[wid] = c;
            __syncthreads();
            c = 0;
#pragma unroll
            for (int w = 0; w < NWARP; ++w) c += s_wn[w];
            if (c >= k) lo = mid; else hi = mid;
            __syncthreads();
        }
        // sum strictly above threshold + exact tie handling at threshold
        float t = __uint_as_float(lo);
        float ssum = 0.0f;
        int cgt = 0;
        for (int a = tid; a < AA; a += NT) {
            float v = s_aux[a];
            if (__float_as_uint(v) > lo) { ssum += v; cgt++; }
        }
#pragma unroll
        for (int o = 16; o; o >>= 1) {
            ssum += __shfl_xor_sync(0xFFFFFFFFu, ssum, o);
            cgt  += __shfl_xor_sync(0xFFFFFFFFu, cgt, o);
        }
        if (lane == 0) { s_wloc[wid] = ssum; s_wn[wid] = cgt; }
        __syncthreads();
        float stot = 0.0f;
        int ctot = 0;
#pragma unroll
        for (int w = 0; w < NWARP; ++w) { stot += s_wloc[w]; ctot += s_wn[w]; }
        topk = stot + (float)(k - ctot) * t;
    }

    if (tid == 0) {
        d_loc[b]  = tot_loc;
        d_cls[b]  = tot_clspos + topk;
        d_npos[b] = tot_npos;
    }
}

__global__ void mb_finalize_kernel(float* __restrict__ out) {
    __shared__ float sl[4], sc[4];
    __shared__ int sn[4];
    int t = threadIdx.x;   // 128 threads
    float l = d_loc[t];
    float c = d_cls[t];
    int   n = d_npos[t];
#pragma unroll
    for (int o = 16; o; o >>= 1) {
        l += __shfl_xor_sync(0xFFFFFFFFu, l, o);
        c += __shfl_xor_sync(0xFFFFFFFFu, c, o);
        n += __shfl_xor_sync(0xFFFFFFFFu, n, o);
    }
    int w = t >> 5;
    if ((t & 31) == 0) { sl[w] = l; sc[w] = c; sn[w] = n; }
    __syncthreads();
    if (t == 0) {
        float L = sl[0] + sl[1] + sl[2] + sl[3];
        float C2 = sc[0] + sc[1] + sc[2] + sc[3];
        float N = (float)(sn[0] + sn[1] + sn[2] + sn[3]);
        out[0] = L / N;
        out[1] = C2 / N;
    }
}

extern "C" void kernel_launch(void* const* d_in, const int* in_sizes, int n_in,
                              void* d_out, int out_size) {
    const float4* pred_off  = (const float4*)d_in[0];
    const float*  pred_conf = (const float*)d_in[1];
    const float4* tboxes    = (const float4*)d_in[2];
    const int*    tlabels   = (const int*)d_in[3];
    const float4* anchors   = (const float4*)d_in[4];
    float* out = (float*)d_out;

    mb_match_kernel<<<BB, NT>>>(pred_off, pred_conf, tboxes, tlabels, anchors);
    mb_finalize_kernel<<<1, BB>>>(out);
}

// round 2
// speedup vs baseline: 1.5278x; 1.5278x over previous
#include <cuda_runtime.h>

#define BB 128
#define GG 16
#define AA 8732
#define CC 21
#define NT 512
#define NWARP (NT/32)
#define NCHUNK ((AA + 31) / 32)   // 273 warp-chunks of 32 anchors

// Dynamic smem: s_aux (AA floats) | s_conf (NWARP*672 floats) | s_meta (AA bytes)
#define SMEM_BYTES (((AA + NWARP * 672) * 4 + AA + 15) & ~15)

__device__ float d_loc[BB];
__device__ float d_cls[BB];
__device__ int   d_npos[BB];
__device__ unsigned d_ctr = 0;   // wraps back to 0 every call -> deterministic across graph replays

__device__ __forceinline__ float smooth_l1(float d) {
    float ad = fabsf(d);
    return ad < 1.0f ? 0.5f * d * d : ad - 0.5f;
}

__global__ __launch_bounds__(NT) void mb_kernel(
    const float4* __restrict__ pred_off,   // [B, A, 4]
    const float*  __restrict__ pred_conf,  // [B, A, C]
    const float4* __restrict__ tboxes,     // [B, G, 4] point form
    const int*    __restrict__ tlabels,    // [B, G]
    const float4* __restrict__ anchors,    // [A, 4] cx,cy,w,h
    float* __restrict__ out)
{
    const int b    = blockIdx.x;
    const int tid  = threadIdx.x;
    const int wid  = tid >> 5;
    const int lane = tid & 31;

    extern __shared__ float smem_f[];
    float* s_aux  = smem_f;                    // [AA]
    float* s_conf = s_aux + AA;                // [NWARP][672]
    unsigned char* s_meta = (unsigned char*)(s_conf + NWARP * 672); // [AA]

    __shared__ float4 s_box[GG];
    __shared__ int s_lab[GG];
    __shared__ unsigned long long s_best[GG];
    __shared__ int s_hist[256];
    __shared__ float s_wf[NWARP];
    __shared__ float s_wf2[NWARP];
    __shared__ int   s_wi[NWARP];
    __shared__ unsigned s_prefix;
    __shared__ int s_rem;
    __shared__ int s_k;
    __shared__ int s_islast;

    if (tid < GG) {
        s_box[tid]  = tboxes[b * GG + tid];
        s_lab[tid]  = tlabels[b * GG + tid];
        s_best[tid] = 0ull;
    }
    if (tid < 256) s_hist[tid] = 0;
    __syncthreads();

    // ---------------- Phase 1: IoU matching ----------------
    unsigned long long lbest[GG];
#pragma unroll
    for (int g = 0; g < GG; ++g) lbest[g] = 0ull;

    for (int a = tid; a < AA; a += NT) {
        float4 an = anchors[a];
        float ax0 = an.x - an.z * 0.5f;
        float ay0 = an.y - an.w * 0.5f;
        float ax1 = an.x + an.z * 0.5f;
        float ay1 = an.y + an.w * 0.5f;
        float area_b = (ax1 - ax0) * (ay1 - ay0);
        float best = -1.0f;
        int bg = 0;
#pragma unroll
        for (int g = 0; g < GG; ++g) {
            float4 bx = s_box[g];
            float w = fminf(bx.z, ax1) - fmaxf(bx.x, ax0);
            float h = fminf(bx.w, ay1) - fmaxf(bx.y, ay0);
            w = fmaxf(w, 0.0f);
            h = fmaxf(h, 0.0f);
            float inter = w * h;
            float area_a = (bx.z - bx.x) * (bx.w - bx.y);
            float iou = __fdividef(inter, area_a + area_b - inter);
            if (iou > best) { best = iou; bg = g; }   // strict > : first-index tie-break (argmax axis=0)
            unsigned long long key =
                (((unsigned long long)__float_as_uint(iou)) << 32) |
                (unsigned long long)(0xFFFFFFFFu - (unsigned)a);
            if (key > lbest[g]) lbest[g] = key;       // lowest anchor index wins ties
        }
        s_meta[a] = (unsigned char)(bg | (best >= 0.5f ? 0x20 : 0));
    }
#pragma unroll
    for (int g = 0; g < GG; ++g) {
        if (lbest[g] > s_best[g]) atomicMax(&s_best[g], lbest[g]);
    }
    __syncthreads();

    // Sequential forced-match overrides (matches reference's ordered loop)
    if (tid == 0) {
#pragma unroll
        for (int g = 0; g < GG; ++g) {
            unsigned a = 0xFFFFFFFFu - (unsigned)(s_best[g] & 0xFFFFFFFFull);
            s_meta[a] = (unsigned char)(g | 0x20);
        }
    }
    __syncthreads();

    // ---------------- Phase 2: NLL + loc loss (warp-staged coalesced loads) ----------------
    float loc_sum = 0.0f, cls_pos = 0.0f;
    int npos = 0;

    float4* sc4 = (float4*)(s_conf + wid * 672);
    for (int chunk = wid; chunk < NCHUNK; chunk += NWARP) {
        int a0 = chunk << 5;
        int nflt = min(32, AA - a0) * CC;         // 672 or 588 (both /4)
        int n4 = nflt >> 2;                        // 168 or 147
        const float4* g4 = (const float4*)(pred_conf + ((size_t)b * AA + a0) * CC);
#pragma unroll
        for (int i = 0; i < 6; ++i) {
            int idx = lane + i * 32;
            if (idx < n4) sc4[idx] = g4[idx];
        }
        __syncwarp();

        int a = a0 + lane;
        if (a < AA) {
            const float* xp = s_conf + wid * 672 + lane * CC;
            float x[CC];
            float mx = -1e30f;
#pragma unroll
            for (int j = 0; j < CC; ++j) {
                x[j] = xp[j];
                mx = fmaxf(mx, x[j]);
            }
            float s = 0.0f;
#pragma unroll
            for (int j = 0; j < CC; ++j) s += __expf(x[j] - mx);

            unsigned m = s_meta[a];
            int gi   = m & 0x1F;
            bool pos = (m & 0x20) != 0;
            int cls  = pos ? (s_lab[gi] + 1) : 0;
            float xc = x[0];
#pragma unroll
            for (int j = 1; j < CC; ++j) xc = (j == cls) ? x[j] : xc;
            float nll = mx + __logf(s) - xc;

            float aux = pos ? 0.0f : nll;
            s_aux[a] = aux;
            atomicAdd(&s_hist[__float_as_uint(aux) >> 23], 1);  // level-1 radix histogram (fused)

            if (pos) {
                npos++;
                cls_pos += nll;
                float4 an = anchors[a];
                float4 gb = s_box[gi];
                float l0 = ((gb.x + gb.z) * 0.5f - an.x) / (an.z * 0.1f);
                float l1 = ((gb.y + gb.w) * 0.5f - an.y) / (an.w * 0.1f);
                float l2 = __logf((gb.z - gb.x) / an.z) / 0.2f;
                float l3 = __logf((gb.w - gb.y) / an.w) / 0.2f;
                float4 p = pred_off[(size_t)b * AA + a];
                loc_sum += smooth_l1(p.x - l0) + smooth_l1(p.y - l1) +
                           smooth_l1(p.z - l2) + smooth_l1(p.w - l3);
            }
        }
        __syncwarp();
    }

    // Deterministic block reduction
#pragma unroll
    for (int o = 16; o; o >>= 1) {
        loc_sum += __shfl_xor_sync(0xFFFFFFFFu, loc_sum, o);
        cls_pos += __shfl_xor_sync(0xFFFFFFFFu, cls_pos, o);
        npos    += __shfl_xor_sync(0xFFFFFFFFu, npos, o);
    }
    if (lane == 0) { s_wf[wid] = loc_sum; s_wf2[wid] = cls_pos; s_wi[wid] = npos; }
    __syncthreads();

    float tot_loc = 0.0f, tot_clspos = 0.0f;
    int tot_npos = 0;
#pragma unroll
    for (int w = 0; w < NWARP; ++w) {
        tot_loc += s_wf[w];
        tot_clspos += s_wf2[w];
        tot_npos += s_wi[w];
    }
    __syncthreads();

    // ---------------- Phase 3: exact top-k via 4-level radix select ----------------
    // Level-1 walk (histogram already built during phase 2)
    if (tid == 0) {
        int k = min(3 * tot_npos, AA - 1);
        s_k = k;
        int rem = k;
        unsigned pfx = 0;
        if (k > 0) {
            int cum = 0;
            int bin;
            for (bin = 255; bin >= 0; --bin) {
                int h = s_hist[bin];
                if (cum + h >= rem) { rem -= cum; break; }
                cum += h;
            }
            pfx = (unsigned)bin << 23;
        }
        s_prefix = pfx;
        s_rem = rem;
    }
    __syncthreads();

    float topk = 0.0f;
    if (s_k > 0) {
        // 3 refinement levels over remaining 23 bits: [15,23), [7,15), [0,7)
#pragma unroll
        for (int lev = 0; lev < 3; ++lev) {
            const int shift = (lev == 0) ? 15 : (lev == 1) ? 7 : 0;
            const int cmp   = shift + 8;          // 23, 15, 7
            const unsigned mask = (lev < 2) ? 0xFFu : 0x7Fu;

            if (tid < 256) s_hist[tid] = 0;
            __syncthreads();
            unsigned pfx = s_prefix;
            for (int a = tid; a < AA; a += NT) {
                unsigned u = __float_as_uint(s_aux[a]);
                if ((u >> cmp) == (pfx >> cmp))
                    atomicAdd(&s_hist[(u >> shift) & mask], 1);
            }
            __syncthreads();
            if (tid == 0) {
                int rem = s_rem;
                int cum = 0;
                int bin;
                for (bin = (int)mask; bin >= 0; --bin) {
                    int h = s_hist[bin];
                    if (cum + h >= rem) { rem -= cum; break; }
                    cum += h;
                }
                s_prefix = pfx | ((unsigned)bin << shift);
                s_rem = rem;
            }
            __syncthreads();
        }

        // Sum values strictly above exact threshold T; add rem copies of T
        unsigned T = s_prefix;
        float ssum = 0.0f;
        for (int a = tid; a < AA; a += NT) {
            float v = s_aux[a];
            if (__float_as_uint(v) > T) ssum += v;
        }
#pragma unroll
        for (int o = 16; o; o >>= 1) ssum += __shfl_xor_sync(0xFFFFFFFFu, ssum, o);
        if (lane == 0) s_wf[wid] = ssum;
        __syncthreads();
        float stot = 0.0f;
#pragma unroll
        for (int w = 0; w < NWARP; ++w) stot += s_wf[w];
        topk = stot + (float)s_rem * __uint_as_float(T);
    }

    // ---------------- Per-batch partials + last-block finalize ----------------
    if (tid == 0) {
        d_loc[b]  = tot_loc;
        d_cls[b]  = tot_clspos + topk;
        d_npos[b] = tot_npos;
        __threadfence();
        unsigned old = atomicInc(&d_ctr, BB - 1);   // wraps to 0 after BB increments
        s_islast = (old == BB - 1) ? 1 : 0;
    }
    __syncthreads();

    if (s_islast && tid < BB) {
        float l = __ldcg(&d_loc[tid]);
        float c = __ldcg(&d_cls[tid]);
        int   n = __ldcg(&d_npos[tid]);
#pragma unroll
        for (int o = 16; o; o >>= 1) {
            l += __shfl_xor_sync(0xFFFFFFFFu, l, o);
            c += __shfl_xor_sync(0xFFFFFFFFu, c, o);
            n += __shfl_xor_sync(0xFFFFFFFFu, n, o);
        }
        if ((tid & 31) == 0) { s_wf[tid >> 5] = l; s_wf2[tid >> 5] = c; s_wi[tid >> 5] = n; }
        __syncwarp();
        if (tid == 0) {
            float L = s_wf[0] + s_wf[1] + s_wf[2] + s_wf[3];
            float C2 = s_wf2[0] + s_wf2[1] + s_wf2[2] + s_wf2[3];
            float N = (float)(s_wi[0] + s_wi[1] + s_wi[2] + s_wi[3]);
            out[0] = L / N;
            out[1] = C2 / N;
        }
    }
}

extern "C" void kernel_launch(void* const* d_in, const int* in_sizes, int n_in,
                              void* d_out, int out_size) {
    const float4* pred_off  = (const float4*)d_in[0];
    const float*  pred_conf = (const float*)d_in[1];
    const float4* tboxes    = (const float4*)d_in[2];
    const int*    tlabels   = (const int*)d_in[3];
    const float4* anchors   = (const float4*)d_in[4];
    float* out = (float*)d_out;

    cudaFuncSetAttribute(mb_kernel, cudaFuncAttributeMaxDynamicSharedMemorySize, SMEM_BYTES);
    mb_kernel<<<BB, NT, SMEM_BYTES>>>(pred_off, pred_conf, tboxes, tlabels, anchors, out);
}